// round 2
// baseline (speedup 1.0000x reference)
#include <cuda_runtime.h>
#include <cstdint>

// SparseUncompressConvolution: fused banded GEMM
//   even w=2j   : lq + relu(W1*U[j] + b) + U[j]/3
//   odd  w=2j+1 : lq + relu(W0*U[j] + W2*U[j+1] + b) + (U[j]+U[j+1])/3
// U rows r = (b*8+h)*1024 + j ; boundary: U[j+1] term dropped when (r+1)%1024==0.

#define BM 64
#define BN 64
#define BK 16
#define BKP 17   // pad for conflict-free LDS

__global__ __launch_bounds__(256, 2)
void suc_gemm_kernel(const float* __restrict__ lq,    // (32,2048,512)
                     const float* __restrict__ U,     // (32768,512)
                     const float* __restrict__ W,     // (512,1536) row-major [do][k*512+dd]
                     const float* __restrict__ bias,  // (512)
                     float* __restrict__ out)         // (32,2048,512)
{
    __shared__ float As[BM + 1][BKP];
    __shared__ float Ws0[BN][BKP];
    __shared__ float Ws1[BN][BKP];
    __shared__ float Ws2[BN][BKP];

    const int n0 = blockIdx.x * BN;   // output-channel tile
    const int r0 = blockIdx.y * BM;   // U-row tile (BM divides 1024 -> tile never crosses a (b,h) group)
    const int tid = threadIdx.x;
    const int tx = tid & 15;          // column group (strided columns: n0 + tx + 16*c)
    const int ty = tid >> 4;          // row group    (rows r0 + ty*4 + i)

    // the extra (shifted) row is invalid exactly when the tile ends a 1024-row group
    const bool zero_extra = (((r0 + BM) & 1023) == 0);

    float acc_e[4][4] = {};
    float acc_o[4][4] = {};

    for (int kt = 0; kt < 512; kt += BK) {
        // --- load A tile: BM+1 rows x BK (coalesced over kk) ---
        #pragma unroll
        for (int x = tid; x < (BM + 1) * BK; x += 256) {
            int r  = x / BK;
            int kk = x % BK;
            float v = 0.f;
            if (!(r == BM && zero_extra))
                v = U[(size_t)(r0 + r) * 512 + kt + kk];
            As[r][kk] = v;
        }
        // --- load 3 weight tiles: BN x BK each (rows of W, k-contiguous -> coalesced) ---
        #pragma unroll
        for (int x = tid; x < BN * BK; x += 256) {
            int nn = x / BK;
            int kk = x % BK;
            const float* wrow = W + (size_t)(n0 + nn) * 1536 + kt + kk;
            Ws0[nn][kk] = wrow[0];
            Ws1[nn][kk] = wrow[512];
            Ws2[nn][kk] = wrow[1024];
        }
        __syncthreads();

        #pragma unroll
        for (int kk = 0; kk < BK; kk++) {
            float a[4], a1[4], w0[4], w1[4], w2[4];
            #pragma unroll
            for (int i = 0; i < 4; i++) {
                a[i]  = As[ty * 4 + i][kk];
                a1[i] = As[ty * 4 + i + 1][kk];
                w0[i] = Ws0[tx + 16 * i][kk];
                w1[i] = Ws1[tx + 16 * i][kk];
                w2[i] = Ws2[tx + 16 * i][kk];
            }
            #pragma unroll
            for (int i = 0; i < 4; i++) {
                #pragma unroll
                for (int c = 0; c < 4; c++) {
                    acc_e[i][c] += a[i]  * w1[c];
                    acc_o[i][c] += a[i]  * w0[c];
                    acc_o[i][c] += a1[i] * w2[c];
                }
            }
        }
        __syncthreads();
    }

    // --- epilogue: bias + relu + residual + res_connect, fused writeback ---
    const int bh    = r0 >> 10;            // r0 / 1024
    const int jbase = (r0 & 1023) + ty * 4;

    #pragma unroll
    for (int i = 0; i < 4; i++) {
        const int j  = jbase + i;              // local row within group (0..1023)
        const int rg = bh * 1024 + j;          // global U row
        const bool valid1 = (j + 1 < 1024);
        const size_t base_e = ((size_t)bh * 2048 + 2 * j) * 512;  // even w = 2j
        const size_t base_o = base_e + 512;                        // odd  w = 2j+1
        #pragma unroll
        for (int c = 0; c < 4; c++) {
            const int dof = n0 + tx + 16 * c;
            const float b_ = bias[dof];
            const float u0 = U[(size_t)rg * 512 + dof];
            const float u1 = valid1 ? U[(size_t)(rg + 1) * 512 + dof] : 0.f;
            const float oe = fmaxf(acc_e[i][c] + b_, 0.f);
            const float oo = fmaxf(acc_o[i][c] + b_, 0.f);
            out[base_e + dof] = lq[base_e + dof] + oe + u0 * (1.f / 3.f);
            out[base_o + dof] = lq[base_o + dof] + oo + (u0 + u1) * (1.f / 3.f);
        }
    }
}

extern "C" void kernel_launch(void* const* d_in, const int* in_sizes, int n_in,
                              void* d_out, int out_size)
{
    const float* lq   = (const float*)d_in[0];  // layer_query (4,8,2048,512)
    const float* U    = (const float*)d_in[1];  // uncompress_in (4,8,1024,512)
    const float* W    = (const float*)d_in[2];  // (512,1536)
    const float* bias = (const float*)d_in[3];  // (512)
    // d_in[4] = i (unused)

    dim3 grid(512 / BN, 32768 / BM);  // (8, 512)
    suc_gemm_kernel<<<grid, 256>>>(lq, U, W, bias, (float*)d_out);
}

// round 4
// speedup vs baseline: 2.7565x; 2.7565x over previous
#include <cuda_runtime.h>
#include <cstdint>

// ============================================================================
// SparseUncompressConvolution via mma.sync tf32 (legacy tensor path, works on
// baseline sm_103 PTX target — tcgen05 is rejected by this build pipeline).
//   even w=2j   : lq + relu(W1*U[j] + b) + U[j]/3
//   odd  w=2j+1 : lq + relu(W0*U[j] + W2*U[j+1] + b) + (U[j]+U[j+1])/3
// Acc_even = A*W1^T ; Acc_odd = A*W0^T + A_shift*W2^T (A_shift = A rows +1)
// ============================================================================

#define BM 128
#define BN 64
#define BK 32
#define NCHUNK 16              // 512 / BK
#define ROWSTRIDE 144          // (BK+4)*4 bytes, conflict-free & 16B aligned
#define A_BYTES (129 * ROWSTRIDE)              // 18576
#define B_BAND_BYTES (64 * ROWSTRIDE)          // 9216
#define B_BYTES (3 * B_BAND_BYTES)             // 27648
#define STAGE (A_BYTES + B_BYTES)              // 46224
#define SMEM_BYTES (2 * STAGE)                 // 92448
#define A_CNT 1032             // 129 rows * 8 x16B
#define TOT_CNT (A_CNT + 1536) // + 3*64*8 x16B

// tf32-rounded copies of U and W (scratch; __device__ globals are allowed)
__device__ float g_Ur[32768 * 512];
__device__ float g_Wr[512 * 1536];

__device__ __forceinline__ uint32_t s2u(const void* p) {
    uint32_t a;
    asm("{ .reg .u64 t; cvta.to.shared.u64 t, %1; cvt.u32.u64 %0, t; }" : "=r"(a) : "l"(p));
    return a;
}
__device__ __forceinline__ float tf32r(float x) {
    float y;
    asm("cvt.rna.tf32.f32 %0, %1;" : "=f"(y) : "f"(x));
    return y;
}
__device__ __forceinline__ void cp16(uint32_t dst, const float* src) {
    asm volatile("cp.async.cg.shared.global [%0], [%1], 16;" :: "r"(dst), "l"(src));
}
__device__ __forceinline__ void cp_commit() {
    asm volatile("cp.async.commit_group;");
}
template <int N> __device__ __forceinline__ void cp_wait() {
    asm volatile("cp.async.wait_group %0;" :: "n"(N));
}
__device__ __forceinline__ void ldsm4(uint32_t addr, uint32_t* r) {
    asm volatile("ldmatrix.sync.aligned.m8n8.x4.shared.b16 {%0,%1,%2,%3}, [%4];"
                 : "=r"(r[0]), "=r"(r[1]), "=r"(r[2]), "=r"(r[3]) : "r"(addr));
}
__device__ __forceinline__ void mma8(float* d, const uint32_t* a, uint32_t b0, uint32_t b1) {
    asm volatile(
        "mma.sync.aligned.m16n8k8.row.col.f32.tf32.tf32.f32 "
        "{%0,%1,%2,%3}, {%4,%5,%6,%7}, {%8,%9}, {%0,%1,%2,%3};"
        : "+f"(d[0]), "+f"(d[1]), "+f"(d[2]), "+f"(d[3])
        : "r"(a[0]), "r"(a[1]), "r"(a[2]), "r"(a[3]), "r"(b0), "r"(b1));
}

// ---------------------------------------------------------------------------
__global__ void __launch_bounds__(256) tf32_round_kernel(const float* __restrict__ s,
                                                         float* __restrict__ d, int n4) {
    int i = blockIdx.x * blockDim.x + threadIdx.x;
    if (i < n4) {
        float4 v = ((const float4*)s)[i];
        v.x = tf32r(v.x); v.y = tf32r(v.y); v.z = tf32r(v.z); v.w = tf32r(v.w);
        ((float4*)d)[i] = v;
    }
}

// ---------------------------------------------------------------------------
__global__ void __launch_bounds__(256, 2)
suc_mma_kernel(const float* __restrict__ lq, const float* __restrict__ U,
               const float* __restrict__ bias, float* __restrict__ out)
{
    extern __shared__ __align__(16) char smem[];
    const uint32_t sb = s2u(smem);
    const int tid = threadIdx.x;
    const int lane = tid & 31;
    const int wid = tid >> 5;
    const int wm = wid & 3;          // warp row block (32 rows each)
    const int wn = wid >> 2;         // warp col block (32 cols each)
    const int n0 = blockIdx.x * BN;
    const int r0 = blockIdx.y * BM;
    const bool zb = (((r0 + BM) & 1023) == 0);   // shifted row 128 invalid

    // zero shifted-extra row (row 128) of both stages when at a group boundary
    if (zb && tid < 64) {
        int s = tid >> 5, w = tid & 31;
        ((float*)(smem + s * STAGE + 128 * ROWSTRIDE))[w] = 0.f;
    }

    // ---- cp.async tile loader ----
    auto issue_load = [&](int c, int s) {
        const int kt = c * BK;
        const uint32_t stb = sb + s * STAGE;
        #pragma unroll 1
        for (int i = tid; i < TOT_CNT; i += 256) {
            if (i < A_CNT) {
                int r = i >> 3, cc = i & 7;
                if (!(zb && r == 128))
                    cp16(stb + r * ROWSTRIDE + cc * 16,
                         &g_Ur[(r0 + r) * 512 + kt + cc * 4]);
            } else {
                int b = i - A_CNT;
                int band = b >> 9, rem = b & 511, n = rem >> 3, cc = rem & 7;
                cp16(stb + A_BYTES + band * B_BAND_BYTES + n * ROWSTRIDE + cc * 16,
                     &g_Wr[(n0 + n) * 1536 + band * 512 + kt + cc * 4]);
            }
        }
        cp_commit();
    };

    // ---- precomputed ldmatrix per-lane address offsets ----
    // A (m16k8 as 16x16 b16, x4): lanes 0-15 -> rows 0..15, lanes 16-31 -> +16B (k+4)
    uint32_t aoff[2];
    #pragma unroll
    for (int mt = 0; mt < 2; mt++)
        aoff[mt] = (wm * 32 + mt * 16 + (lane & 15)) * ROWSTRIDE + (lane >> 4) * 16;
    // B (pairs of n8k8): rows = n, words = k
    uint32_t boff[3][2];
    #pragma unroll
    for (int band = 0; band < 3; band++)
        #pragma unroll
        for (int p = 0; p < 2; p++)
            boff[band][p] = A_BYTES + band * B_BAND_BYTES
                + (wn * 32 + p * 16 + (lane & 7) + ((lane >> 4) & 1) * 8) * ROWSTRIDE
                + ((lane >> 3) & 1) * 16;

    float ae[2][4][4] = {};
    float ao[2][4][4] = {};

    issue_load(0, 0);
    issue_load(1, 1);

    #pragma unroll 1
    for (int c = 0; c < NCHUNK; ++c) {
        if (c < NCHUNK - 1) cp_wait<1>(); else cp_wait<0>();
        __syncthreads();

        const uint32_t stb = sb + (c & 1) * STAGE;
        #pragma unroll
        for (int k8 = 0; k8 < 4; k8++) {
            const uint32_t ko = k8 * 32;
            uint32_t a[2][4], as[2][4];
            #pragma unroll
            for (int mt = 0; mt < 2; mt++) {
                ldsm4(stb + aoff[mt] + ko, a[mt]);
                ldsm4(stb + aoff[mt] + ROWSTRIDE + ko, as[mt]);   // +1 row shift
            }
            // band 1 -> even acc (A)
            {
                uint32_t b[2][4];
                ldsm4(stb + boff[1][0] + ko, b[0]);
                ldsm4(stb + boff[1][1] + ko, b[1]);
                #pragma unroll
                for (int mt = 0; mt < 2; mt++)
                    #pragma unroll
                    for (int nt = 0; nt < 4; nt++)
                        mma8(ae[mt][nt], a[mt], b[nt >> 1][(nt & 1) * 2],
                             b[nt >> 1][(nt & 1) * 2 + 1]);
            }
            // band 0 -> odd acc (A)
            {
                uint32_t b[2][4];
                ldsm4(stb + boff[0][0] + ko, b[0]);
                ldsm4(stb + boff[0][1] + ko, b[1]);
                #pragma unroll
                for (int mt = 0; mt < 2; mt++)
                    #pragma unroll
                    for (int nt = 0; nt < 4; nt++)
                        mma8(ao[mt][nt], a[mt], b[nt >> 1][(nt & 1) * 2],
                             b[nt >> 1][(nt & 1) * 2 + 1]);
            }
            // band 2 -> odd acc (A shifted)
            {
                uint32_t b[2][4];
                ldsm4(stb + boff[2][0] + ko, b[0]);
                ldsm4(stb + boff[2][1] + ko, b[1]);
                #pragma unroll
                for (int mt = 0; mt < 2; mt++)
                    #pragma unroll
                    for (int nt = 0; nt < 4; nt++)
                        mma8(ao[mt][nt], as[mt], b[nt >> 1][(nt & 1) * 2],
                             b[nt >> 1][(nt & 1) * 2 + 1]);
            }
        }
        __syncthreads();
        if (c + 2 < NCHUNK) issue_load(c + 2, c & 1);
    }

    // ---- fused epilogue: bias + relu + residual + res_connect ----
    const int l4 = lane >> 2;
    const int l2 = (lane & 3) * 2;
    #pragma unroll
    for (int mt = 0; mt < 2; mt++) {
        #pragma unroll
        for (int h = 0; h < 2; h++) {
            const int rg = r0 + wm * 32 + mt * 16 + h * 8 + l4;
            const int j = rg & 1023;
            const int bh = rg >> 10;
            const bool v1 = (j != 1023);
            const int ie_base = (bh * 2048 + 2 * j) * 512;
            #pragma unroll
            for (int nt = 0; nt < 4; nt++) {
                const int dof = n0 + wn * 32 + nt * 8 + l2;
                const float2 u0 = *(const float2*)&U[rg * 512 + dof];
                float2 u1 = make_float2(0.f, 0.f);
                if (v1) u1 = *(const float2*)&U[(rg + 1) * 512 + dof];
                const float2 bv = *(const float2*)&bias[dof];
                const int ie = ie_base + dof;
                const int io = ie + 512;
                const float2 lqe = *(const float2*)&lq[ie];
                const float2 lqo = *(const float2*)&lq[io];
                const float e0 = ae[mt][nt][h * 2 + 0], e1 = ae[mt][nt][h * 2 + 1];
                const float o0 = ao[mt][nt][h * 2 + 0], o1 = ao[mt][nt][h * 2 + 1];
                float2 re, ro;
                re.x = lqe.x + fmaxf(e0 + bv.x, 0.f) + u0.x * (1.f / 3.f);
                re.y = lqe.y + fmaxf(e1 + bv.y, 0.f) + u0.y * (1.f / 3.f);
                ro.x = lqo.x + fmaxf(o0 + bv.x, 0.f) + (u0.x + u1.x) * (1.f / 3.f);
                ro.y = lqo.y + fmaxf(o1 + bv.y, 0.f) + (u0.y + u1.y) * (1.f / 3.f);
                *(float2*)&out[ie] = re;
                *(float2*)&out[io] = ro;
            }
        }
    }
}

// ============================================================================
extern "C" void kernel_launch(void* const* d_in, const int* in_sizes, int n_in,
                              void* d_out, int out_size)
{
    const float* lq   = (const float*)d_in[0];  // (4,8,2048,512)
    const float* U    = (const float*)d_in[1];  // (32768,512)
    const float* W    = (const float*)d_in[2];  // (512,1536)
    const float* bias = (const float*)d_in[3];  // (512)

    float* ur; cudaGetSymbolAddress((void**)&ur, g_Ur);
    float* wr; cudaGetSymbolAddress((void**)&wr, g_Wr);

    // pre-round U and W to tf32 (RNA) so the hot loop needs no conversions
    tf32_round_kernel<<<(32768 * 512 / 4 + 255) / 256, 256>>>(U, ur, 32768 * 512 / 4);
    tf32_round_kernel<<<(512 * 1536 / 4 + 255) / 256, 256>>>(W, wr, 512 * 1536 / 4);

    cudaFuncSetAttribute(suc_mma_kernel, cudaFuncAttributeMaxDynamicSharedMemorySize,
                         SMEM_BYTES);
    dim3 grid(512 / BN, 32768 / BM);  // (8, 256)
    suc_mma_kernel<<<grid, 256, SMEM_BYTES>>>(lq, U, bias, (float*)d_out);
}

// round 5
// speedup vs baseline: 6.7832x; 2.4608x over previous
#include <cuda_runtime.h>
#include <cuda_fp16.h>
#include <cstdint>

// ============================================================================
// SparseUncompressConvolution via mma.sync fp16 (m16n8k16, fp32 accumulate).
// fp16 mantissa == tf32 mantissa (10 bits) -> same accuracy, 2x MACs/instr.
//   even w=2j   : lq + relu(W1*U[j] + b) + U[j]/3
//   odd  w=2j+1 : lq + relu(W0*U[j] + W2*U[j+1] + b) + (U[j]+U[j+1])/3
// Acc_even = A*W1^T ; Acc_odd = A*W0^T + A_shift*W2^T (A_shift = A rows +1)
// ============================================================================

#define BM 128
#define BN 64
#define BK 64                  // fp16 elems per chunk = 128 bytes per row
#define NCHUNK 8               // 512 / BK
#define ROWSTRIDE 144          // 128B data + 16B pad (conflict-free ldmatrix)
#define A_BYTES (129 * ROWSTRIDE)
#define B_BAND_BYTES (64 * ROWSTRIDE)
#define STAGE (A_BYTES + 3 * B_BAND_BYTES)     // 46224
#define SMEM_BYTES (2 * STAGE)                 // 92448
#define A_CNT 1032             // 129 rows * 8 x16B chunks
#define TOT_CNT (A_CNT + 1536) // + 3*64*8

// fp16 copies of U and W (scratch via __device__ globals)
__device__ __half g_Uh[32768 * 512];
__device__ __half g_Wh[512 * 1536];

__device__ __forceinline__ uint32_t s2u(const void* p) {
    uint32_t a;
    asm("{ .reg .u64 t; cvta.to.shared.u64 t, %1; cvt.u32.u64 %0, t; }" : "=r"(a) : "l"(p));
    return a;
}
__device__ __forceinline__ void cp16(uint32_t dst, const void* src) {
    asm volatile("cp.async.cg.shared.global [%0], [%1], 16;" :: "r"(dst), "l"(src));
}
__device__ __forceinline__ void cp_commit() { asm volatile("cp.async.commit_group;"); }
template <int N> __device__ __forceinline__ void cp_wait() {
    asm volatile("cp.async.wait_group %0;" :: "n"(N));
}
__device__ __forceinline__ void ldsm4(uint32_t addr, uint32_t* r) {
    asm volatile("ldmatrix.sync.aligned.m8n8.x4.shared.b16 {%0,%1,%2,%3}, [%4];"
                 : "=r"(r[0]), "=r"(r[1]), "=r"(r[2]), "=r"(r[3]) : "r"(addr));
}
__device__ __forceinline__ void mma16(float* d, const uint32_t* a, uint32_t b0, uint32_t b1) {
    asm volatile(
        "mma.sync.aligned.m16n8k16.row.col.f32.f16.f16.f32 "
        "{%0,%1,%2,%3}, {%4,%5,%6,%7}, {%8,%9}, {%0,%1,%2,%3};"
        : "+f"(d[0]), "+f"(d[1]), "+f"(d[2]), "+f"(d[3])
        : "r"(a[0]), "r"(a[1]), "r"(a[2]), "r"(a[3]), "r"(b0), "r"(b1));
}

// ---------------------------------------------------------------------------
__global__ void __launch_bounds__(256) f2h_kernel(const float* __restrict__ s,
                                                  __half* __restrict__ d, int n4) {
    int i = blockIdx.x * blockDim.x + threadIdx.x;
    if (i < n4) {
        float4 v = ((const float4*)s)[i];
        __half2 lo = __floats2half2_rn(v.x, v.y);
        __half2 hi = __floats2half2_rn(v.z, v.w);
        uint2 pk;
        pk.x = *(uint32_t*)&lo;
        pk.y = *(uint32_t*)&hi;
        ((uint2*)d)[i] = pk;
    }
}

// ---------------------------------------------------------------------------
__global__ void __launch_bounds__(256, 2)
suc_mma_kernel(const float* __restrict__ lq, const float* __restrict__ U,
               const float* __restrict__ bias, float* __restrict__ out)
{
    extern __shared__ __align__(16) char smem[];
    const uint32_t sb = s2u(smem);
    const int tid = threadIdx.x;
    const int lane = tid & 31;
    const int wid = tid >> 5;
    const int wm = wid & 3;          // warp row block (32 rows)
    const int wn = wid >> 2;         // warp col block (32 cols)
    const int n0 = blockIdx.x * BN;
    const int r0 = blockIdx.y * BM;
    const bool zb = (((r0 + BM) & 1023) == 0);   // shifted row 128 invalid

    // zero shifted-extra row (row 128, 128B) of both stages at group boundary
    if (zb && tid < 64) {
        int s = tid >> 5, w = tid & 31;
        ((uint32_t*)(smem + s * STAGE + 128 * ROWSTRIDE))[w] = 0u;
    }

    auto issue_load = [&](int c, int s) {
        const int kt = c * BK;
        const uint32_t stb = sb + s * STAGE;
        #pragma unroll 1
        for (int i = tid; i < TOT_CNT; i += 256) {
            if (i < A_CNT) {
                int r = i >> 3, cc = i & 7;
                if (!(zb && r == 128))
                    cp16(stb + r * ROWSTRIDE + cc * 16,
                         &g_Uh[(r0 + r) * 512 + kt + cc * 8]);
            } else {
                int b = i - A_CNT;
                int band = b >> 9, rem = b & 511, n = rem >> 3, cc = rem & 7;
                cp16(stb + A_BYTES + band * B_BAND_BYTES + n * ROWSTRIDE + cc * 16,
                     &g_Wh[(n0 + n) * 1536 + band * 512 + kt + cc * 8]);
            }
        }
        cp_commit();
    };

    // A fragment (m16k16 halves): lanes 0-15 rows m0-15, lanes 16-31 +16B k-offset
    uint32_t aoff[2];
    #pragma unroll
    for (int mt = 0; mt < 2; mt++)
        aoff[mt] = (wm * 32 + mt * 16 + (lane & 15)) * ROWSTRIDE + (lane >> 4) * 16;
    // B fragment pairs (n16 x k16 per x4): rows = n, 16B chunks = k halves
    uint32_t boff[3][2];
    #pragma unroll
    for (int band = 0; band < 3; band++)
        #pragma unroll
        for (int p = 0; p < 2; p++)
            boff[band][p] = A_BYTES + band * B_BAND_BYTES
                + (wn * 32 + p * 16 + (lane & 7) + ((lane >> 4) & 1) * 8) * ROWSTRIDE
                + ((lane >> 3) & 1) * 16;

    float ae[2][4][4] = {};
    float ao[2][4][4] = {};

    issue_load(0, 0);
    issue_load(1, 1);

    #pragma unroll 1
    for (int c = 0; c < NCHUNK; ++c) {
        if (c < NCHUNK - 1) cp_wait<1>(); else cp_wait<0>();
        __syncthreads();

        const uint32_t stb = sb + (c & 1) * STAGE;
        #pragma unroll
        for (int g = 0; g < 4; g++) {           // 4 x k16 per BK=64 chunk
            const uint32_t ko = g * 32;         // 16 halves = 32B
            uint32_t a[2][4], as[2][4];
            #pragma unroll
            for (int mt = 0; mt < 2; mt++) {
                ldsm4(stb + aoff[mt] + ko, a[mt]);
                ldsm4(stb + aoff[mt] + ROWSTRIDE + ko, as[mt]);   // +1 row shift
            }
            uint32_t b1[2][4], b0[2][4], b2[2][4];
            ldsm4(stb + boff[1][0] + ko, b1[0]);
            ldsm4(stb + boff[1][1] + ko, b1[1]);
            ldsm4(stb + boff[0][0] + ko, b0[0]);
            ldsm4(stb + boff[0][1] + ko, b0[1]);
            ldsm4(stb + boff[2][0] + ko, b2[0]);
            ldsm4(stb + boff[2][1] + ko, b2[1]);
            #pragma unroll
            for (int mt = 0; mt < 2; mt++)
                #pragma unroll
                for (int nt = 0; nt < 4; nt++) {
                    const int hp = nt >> 1, hq = (nt & 1) * 2;
                    mma16(ae[mt][nt], a[mt],  b1[hp][hq], b1[hp][hq + 1]); // even
                    mma16(ao[mt][nt], a[mt],  b0[hp][hq], b0[hp][hq + 1]); // odd A
                    mma16(ao[mt][nt], as[mt], b2[hp][hq], b2[hp][hq + 1]); // odd A+1
                }
        }
        __syncthreads();
        if (c + 2 < NCHUNK) issue_load(c + 2, c & 1);
    }

    // ---- fused epilogue: bias + relu + residual + res_connect ----
    const int l4 = lane >> 2;
    const int l2 = (lane & 3) * 2;
    #pragma unroll
    for (int mt = 0; mt < 2; mt++) {
        #pragma unroll
        for (int h = 0; h < 2; h++) {
            const int rg = r0 + wm * 32 + mt * 16 + h * 8 + l4;
            const int j = rg & 1023;
            const int bh = rg >> 10;
            const bool v1 = (j != 1023);
            const int ie_base = (bh * 2048 + 2 * j) * 512;
            #pragma unroll
            for (int nt = 0; nt < 4; nt++) {
                const int dof = n0 + wn * 32 + nt * 8 + l2;
                const float2 u0 = *(const float2*)&U[rg * 512 + dof];
                float2 u1 = make_float2(0.f, 0.f);
                if (v1) u1 = *(const float2*)&U[(rg + 1) * 512 + dof];
                const float2 bv = *(const float2*)&bias[dof];
                const int ie = ie_base + dof;
                const int io = ie + 512;
                const float2 lqe = *(const float2*)&lq[ie];
                const float2 lqo = *(const float2*)&lq[io];
                const float e0 = ae[mt][nt][h * 2 + 0], e1 = ae[mt][nt][h * 2 + 1];
                const float o0 = ao[mt][nt][h * 2 + 0], o1 = ao[mt][nt][h * 2 + 1];
                float2 re, ro;
                re.x = lqe.x + fmaxf(e0 + bv.x, 0.f) + u0.x * (1.f / 3.f);
                re.y = lqe.y + fmaxf(e1 + bv.y, 0.f) + u0.y * (1.f / 3.f);
                ro.x = lqo.x + fmaxf(o0 + bv.x, 0.f) + (u0.x + u1.x) * (1.f / 3.f);
                ro.y = lqo.y + fmaxf(o1 + bv.y, 0.f) + (u0.y + u1.y) * (1.f / 3.f);
                *(float2*)&out[ie] = re;
                *(float2*)&out[io] = ro;
            }
        }
    }
}

// ============================================================================
extern "C" void kernel_launch(void* const* d_in, const int* in_sizes, int n_in,
                              void* d_out, int out_size)
{
    const float* lq   = (const float*)d_in[0];  // (4,8,2048,512)
    const float* U    = (const float*)d_in[1];  // (32768,512)
    const float* W    = (const float*)d_in[2];  // (512,1536)
    const float* bias = (const float*)d_in[3];  // (512)

    __half* uh; cudaGetSymbolAddress((void**)&uh, g_Uh);
    __half* wh; cudaGetSymbolAddress((void**)&wh, g_Wh);

    f2h_kernel<<<(32768 * 512 / 4 + 255) / 256, 256>>>(U, uh, 32768 * 512 / 4);
    f2h_kernel<<<(512 * 1536 / 4 + 255) / 256, 256>>>(W, wh, 512 * 1536 / 4);

    cudaFuncSetAttribute(suc_mma_kernel, cudaFuncAttributeMaxDynamicSharedMemorySize,
                         SMEM_BYTES);
    dim3 grid(512 / BN, 32768 / BM);  // (8, 256)
    suc_mma_kernel<<<grid, 256, SMEM_BYTES>>>(lq, U, bias, (float*)d_out);
}